// round 2
// baseline (speedup 1.0000x reference)
#include <cuda_runtime.h>
#include <cuda_bf16.h>
#include <cstdint>

// Hierarchical-softmax (DeepWalk) loss.
// For each sample b:
//   ve = emb_table[v[b]]  (128 f32)
//   node = (V-1) + u[b]; repeat depth times:
//     parent = (node-1)>>1 ; sign = (node&1) ? +1 : -1 ; node = parent
//     dot = hsoftmax[parent] . ve
//     loss += softplus(-sign*dot)        // = -log_sigmoid(sign*dot)
// One warp per sample. Each lane owns one float4 (4 consecutive floats) of ve.
// All 20 parent indices are pure-integer computable up front, so the 20
// 512B gathers are independent -> full unroll lets ptxas batch LDG.128s.

static __device__ __forceinline__ float softplus_neg(float x) {
    // softplus(x) = max(x,0) + log1p(exp(-|x|)), numerically stable
    return fmaxf(x, 0.0f) + log1pf(__expf(-fabsf(x)));
}

template <int DEPTH>
__global__ __launch_bounds__(256)
void hs_loss_kernel(const float* __restrict__ emb,
                    const float* __restrict__ hs,
                    const int*   __restrict__ u,
                    const int*   __restrict__ v,
                    float*       __restrict__ out,
                    int B, int V)
{
    const int gtid = blockIdx.x * blockDim.x + threadIdx.x;
    const int wid  = gtid >> 5;          // sample index
    const int lane = gtid & 31;
    if (wid >= B) return;

    const int vi = v[wid];
    const int ui = u[wid];

    // v embedding: 32 lanes x float4 = 128 floats, coalesced 512B load
    const float4 ve = reinterpret_cast<const float4*>(emb + (size_t)vi * 128)[lane];

    // Precompute the whole leaf-to-root parent chain (pure integer work)
    int   par[DEPTH];
    float sgn[DEPTH];
    {
        int node = (V - 1) + ui;
        #pragma unroll
        for (int d = 0; d < DEPTH; ++d) {
            par[d] = (node - 1) >> 1;
            sgn[d] = (node & 1) ? 1.0f : -1.0f;
            node   = par[d];
        }
    }

    float loss = 0.0f;
    #pragma unroll
    for (int d = 0; d < DEPTH; ++d) {
        const float4 h =
            reinterpret_cast<const float4*>(hs + (size_t)par[d] * 128)[lane];
        float p = h.x * ve.x + h.y * ve.y + h.z * ve.z + h.w * ve.w;
        // butterfly reduction: every lane ends with the full dot product
        p += __shfl_xor_sync(0xFFFFFFFFu, p, 16);
        p += __shfl_xor_sync(0xFFFFFFFFu, p, 8);
        p += __shfl_xor_sync(0xFFFFFFFFu, p, 4);
        p += __shfl_xor_sync(0xFFFFFFFFu, p, 2);
        p += __shfl_xor_sync(0xFFFFFFFFu, p, 1);
        loss += softplus_neg(-sgn[d] * p);
    }

    if (lane == 0) out[wid] = loss;
}

// Runtime-depth fallback (shouldn't trigger for V = 2^20)
__global__ __launch_bounds__(256)
void hs_loss_kernel_gen(const float* __restrict__ emb,
                        const float* __restrict__ hs,
                        const int*   __restrict__ u,
                        const int*   __restrict__ v,
                        float*       __restrict__ out,
                        int B, int V, int depth)
{
    const int gtid = blockIdx.x * blockDim.x + threadIdx.x;
    const int wid  = gtid >> 5;
    const int lane = gtid & 31;
    if (wid >= B) return;

    const int vi = v[wid];
    const int ui = u[wid];
    const float4 ve = reinterpret_cast<const float4*>(emb + (size_t)vi * 128)[lane];

    int node = (V - 1) + ui;
    float loss = 0.0f;
    for (int d = 0; d < depth; ++d) {
        const int parent = (node - 1) >> 1;
        const float sg   = (node & 1) ? 1.0f : -1.0f;
        node = parent;
        const float4 h =
            reinterpret_cast<const float4*>(hs + (size_t)parent * 128)[lane];
        float p = h.x * ve.x + h.y * ve.y + h.z * ve.z + h.w * ve.w;
        p += __shfl_xor_sync(0xFFFFFFFFu, p, 16);
        p += __shfl_xor_sync(0xFFFFFFFFu, p, 8);
        p += __shfl_xor_sync(0xFFFFFFFFu, p, 4);
        p += __shfl_xor_sync(0xFFFFFFFFu, p, 2);
        p += __shfl_xor_sync(0xFFFFFFFFu, p, 1);
        loss += softplus_neg(-sg * p);
    }
    if (lane == 0) out[wid] = loss;
}

extern "C" void kernel_launch(void* const* d_in, const int* in_sizes, int n_in,
                              void* d_out, int out_size)
{
    const float* emb = (const float*)d_in[0];   // [V, 128]
    const float* hs  = (const float*)d_in[1];   // [V-1, 128]
    const int*   u   = (const int*)d_in[2];     // [B]
    const int*   v   = (const int*)d_in[3];     // [B]
    float*       out = (float*)d_out;           // [B]

    const int B = in_sizes[2];
    const int V = in_sizes[0] / 128;

    // depth = log2(V) for a complete tree
    int depth = 0;
    while ((1 << (depth + 1)) <= V) ++depth;

    const int threads = 256;                  // 8 warps -> 8 samples per block
    const int blocks  = (B * 32 + threads - 1) / threads;

    if (depth == 20) {
        hs_loss_kernel<20><<<blocks, threads>>>(emb, hs, u, v, out, B, V);
    } else {
        hs_loss_kernel_gen<<<blocks, threads>>>(emb, hs, u, v, out, B, V, depth);
    }
}

// round 3
// speedup vs baseline: 1.3374x; 1.3374x over previous
#include <cuda_runtime.h>
#include <cuda_bf16.h>
#include <cstdint>

// Hierarchical-softmax (DeepWalk) loss.
//   loss[b] = sum_d softplus(-sign_d * (hsoftmax[par_d] . emb_table[v[b]]))
//
// R3 layout: 8 lanes per sample (4 samples per warp).
//   - each lane owns 16 floats (4 float4) of the 128-f32 v embedding
//   - per level: 4 warp-wide LDG.128 cover 4 samples' hsoftmax rows,
//     3-step butterfly shfl reduces each group's dot
//   - softplus is restructured: sum_d log1p(e_d) = log(prod_d (1+e_d)),
//     each factor in (1,2] so prod <= 2^20 (no overflow); one __logf total.
//   - path sign packed into bit31 of the parent index (applied by XOR on
//     the float sign bit of the dot).

template <int DEPTH>
__global__ __launch_bounds__(256)
void hs_loss_g8(const float* __restrict__ emb,
                const float* __restrict__ hs,
                const int*   __restrict__ u,
                const int*   __restrict__ v,
                float*       __restrict__ out,
                int B, int V)
{
    const int tid    = blockIdx.x * blockDim.x + threadIdx.x;
    const int warpId = tid >> 5;
    const int lane   = tid & 31;
    const int group  = lane >> 3;       // 0..3 : sample slot within warp
    const int sub    = lane & 7;        // 0..7 : position within sample group
    const int s      = warpId * 4 + group;
    if (s >= B) return;

    const int vi = v[s];
    const int ui = u[s];

    // v embedding: group reads 4 x 128B contiguous chunks (full-line coalesced)
    const float4* vrow = reinterpret_cast<const float4*>(emb + (size_t)vi * 128);
    const float4 ve0 = vrow[sub];
    const float4 ve1 = vrow[8  + sub];
    const float4 ve2 = vrow[16 + sub];
    const float4 ve3 = vrow[24 + sub];

    // Parent chain, sign packed into bit31: bit31 set  -> flip sign of dot
    // (right child => loss term softplus(+dot) => z = -dot => flip).
    // left child (node odd): z = +dot -> no flip.
    int par[DEPTH];
    {
        int node = (V - 1) + ui;
        #pragma unroll
        for (int d = 0; d < DEPTH; ++d) {
            const int p = (node - 1) >> 1;
            // flip mask: node even (right child) -> 0x80000000
            par[d] = p | ((~node & 1) << 31);
            node = p;
        }
    }

    float maxsum = 0.0f;   // sum of max(-z,0) terms
    float prod   = 1.0f;   // prod of (1 + exp(-|z|))

    #pragma unroll
    for (int d = 0; d < DEPTH; ++d) {
        const int idx  = par[d] & 0x7FFFFFFF;
        const int flip = par[d] & 0x80000000;
        const float4* hrow =
            reinterpret_cast<const float4*>(hs + (size_t)idx * 128);
        const float4 h0 = hrow[sub];
        const float4 h1 = hrow[8  + sub];
        const float4 h2 = hrow[16 + sub];
        const float4 h3 = hrow[24 + sub];

        float p = h0.x * ve0.x + h0.y * ve0.y + h0.z * ve0.z + h0.w * ve0.w
                + h1.x * ve1.x + h1.y * ve1.y + h1.z * ve1.z + h1.w * ve1.w
                + h2.x * ve2.x + h2.y * ve2.y + h2.z * ve2.z + h2.w * ve2.w
                + h3.x * ve3.x + h3.y * ve3.y + h3.z * ve3.z + h3.w * ve3.w;

        // 3-step butterfly within the 8-lane group (xor 4,2,1 stays in-group)
        p += __shfl_xor_sync(0xFFFFFFFFu, p, 4);
        p += __shfl_xor_sync(0xFFFFFFFFu, p, 2);
        p += __shfl_xor_sync(0xFFFFFFFFu, p, 1);

        // z = sign * dot ; loss term = softplus(-z) = max(-z,0) + log1p(e^{-|z|})
        const float z = __int_as_float(__float_as_int(p) ^ flip);
        maxsum += fmaxf(-z, 0.0f);
        const float e = __expf(-fabsf(z));
        prod = __fmaf_rn(prod, e, prod);           // prod *= (1 + e)
    }

    if (sub == 0) out[s] = maxsum + __logf(prod);
}

// Runtime-depth fallback (same g=8 structure, non-unrolled chain)
__global__ __launch_bounds__(256)
void hs_loss_g8_gen(const float* __restrict__ emb,
                    const float* __restrict__ hs,
                    const int*   __restrict__ u,
                    const int*   __restrict__ v,
                    float*       __restrict__ out,
                    int B, int V, int depth)
{
    const int tid    = blockIdx.x * blockDim.x + threadIdx.x;
    const int warpId = tid >> 5;
    const int lane   = tid & 31;
    const int group  = lane >> 3;
    const int sub    = lane & 7;
    const int s      = warpId * 4 + group;
    if (s >= B) return;

    const int vi = v[s];
    const int ui = u[s];
    const float4* vrow = reinterpret_cast<const float4*>(emb + (size_t)vi * 128);
    const float4 ve0 = vrow[sub];
    const float4 ve1 = vrow[8  + sub];
    const float4 ve2 = vrow[16 + sub];
    const float4 ve3 = vrow[24 + sub];

    int node = (V - 1) + ui;
    float maxsum = 0.0f, prod = 1.0f;
    for (int d = 0; d < depth; ++d) {
        const int pidx = (node - 1) >> 1;
        const int flip = (~node & 1) << 31;
        node = pidx;
        const float4* hrow =
            reinterpret_cast<const float4*>(hs + (size_t)pidx * 128);
        const float4 h0 = hrow[sub];
        const float4 h1 = hrow[8  + sub];
        const float4 h2 = hrow[16 + sub];
        const float4 h3 = hrow[24 + sub];

        float p = h0.x * ve0.x + h0.y * ve0.y + h0.z * ve0.z + h0.w * ve0.w
                + h1.x * ve1.x + h1.y * ve1.y + h1.z * ve1.z + h1.w * ve1.w
                + h2.x * ve2.x + h2.y * ve2.y + h2.z * ve2.z + h2.w * ve2.w
                + h3.x * ve3.x + h3.y * ve3.y + h3.z * ve3.z + h3.w * ve3.w;
        p += __shfl_xor_sync(0xFFFFFFFFu, p, 4);
        p += __shfl_xor_sync(0xFFFFFFFFu, p, 2);
        p += __shfl_xor_sync(0xFFFFFFFFu, p, 1);

        const float z = __int_as_float(__float_as_int(p) ^ flip);
        maxsum += fmaxf(-z, 0.0f);
        const float e = __expf(-fabsf(z));
        prod = __fmaf_rn(prod, e, prod);
    }
    if (sub == 0) out[s] = maxsum + __logf(prod);
}

extern "C" void kernel_launch(void* const* d_in, const int* in_sizes, int n_in,
                              void* d_out, int out_size)
{
    const float* emb = (const float*)d_in[0];   // [V, 128]
    const float* hs  = (const float*)d_in[1];   // [V-1, 128]
    const int*   u   = (const int*)d_in[2];     // [B]
    const int*   v   = (const int*)d_in[3];     // [B]
    float*       out = (float*)d_out;           // [B]

    const int B = in_sizes[2];
    const int V = in_sizes[0] / 128;

    int depth = 0;
    while ((1 << (depth + 1)) <= V) ++depth;

    const int threads = 256;                         // 8 warps = 32 samples/block
    const int warps   = (B + 3) / 4;                 // 4 samples per warp
    const int blocks  = (warps * 32 + threads - 1) / threads;

    if (depth == 20) {
        hs_loss_g8<20><<<blocks, threads>>>(emb, hs, u, v, out, B, V);
    } else {
        hs_loss_g8_gen<<<blocks, threads>>>(emb, hs, u, v, out, B, V, depth);
    }
}

// round 5
// speedup vs baseline: 1.5425x; 1.1534x over previous
#include <cuda_runtime.h>
#include <cuda_bf16.h>
#include <cstdint>

// Hierarchical-softmax (DeepWalk) loss.
//   loss[b] = sum_d softplus(-sign_d * (hsoftmax[par_d] . emb_table[v[b]]))
//
// R4: 8 lanes per sample (4 samples/warp), parent chain computed by pure
// shifts of m = V + u (1-based heap index):
//     parent_d = (m >> (d+1)) - 1,   right-child flip_d = (m >> d) & 1
// -> no par[] register array (R3 burned ~20 regs on it, occ 36%).
// Streaming (__ldcs) loads for the no-reuse data: v_emb rows and the 3
// deepest tree levels (working sets >= 64MB >> L2), keeping L2 for the
// mid levels that can actually hit.
// softplus sum folded as: sum log1p(e_d) = log(prod (1+e_d)), one __logf.

template <bool STREAM>
static __device__ __forceinline__ float4 ld4(const float4* p) {
    if (STREAM) return __ldcs(p);
    return __ldg(p);
}

template <int DEPTH>
__global__ __launch_bounds__(256)
void hs_loss_g8(const float* __restrict__ emb,
                const float* __restrict__ hs,
                const int*   __restrict__ u,
                const int*   __restrict__ v,
                float*       __restrict__ out,
                int B, int V)
{
    const int tid    = blockIdx.x * blockDim.x + threadIdx.x;
    const int warpId = tid >> 5;
    const int lane   = tid & 31;
    const int group  = lane >> 3;       // sample slot within warp (0..3)
    const int sub    = lane & 7;        // lane within sample group (0..7)
    const int s      = warpId * 4 + group;
    if (s >= B) return;

    const int vi = v[s];
    const unsigned m = (unsigned)(V + u[s]);   // 1-based heap index of leaf

    // v embedding: 4 x float4 per lane, evict-first (no reuse, 512MB table)
    const float4* vrow = reinterpret_cast<const float4*>(emb + (size_t)vi * 128);
    const float4 ve0 = __ldcs(vrow + sub);
    const float4 ve1 = __ldcs(vrow + 8  + sub);
    const float4 ve2 = __ldcs(vrow + 16 + sub);
    const float4 ve3 = __ldcs(vrow + 24 + sub);

    float maxsum = 0.0f;   // sum of max(-z,0)
    float prod   = 1.0f;   // prod of (1 + exp(-|z|)), each factor in (1,2]

    #pragma unroll
    for (int d = 0; d < DEPTH; ++d) {
        const int idx  = (int)(m >> (d + 1)) - 1;
        const int flip = (int)((m >> d) & 1u) << 31;   // right child -> flip

        const float4* hrow =
            reinterpret_cast<const float4*>(hs + (size_t)idx * 128);
        constexpr bool deep = true;  // selected per-level below
        float4 h0, h1, h2, h3;
        if (d < 3) {   // deepest levels: working set 64-256MB, no L2 hope
            h0 = ld4<deep>(hrow + sub);
            h1 = ld4<deep>(hrow + 8  + sub);
            h2 = ld4<deep>(hrow + 16 + sub);
            h3 = ld4<deep>(hrow + 24 + sub);
        } else {       // mid/top levels: keep cacheable in L2/L1
            h0 = ld4<!deep>(hrow + sub);
            h1 = ld4<!deep>(hrow + 8  + sub);
            h2 = ld4<!deep>(hrow + 16 + sub);
            h3 = ld4<!deep>(hrow + 24 + sub);
        }

        float p = h0.x * ve0.x + h0.y * ve0.y + h0.z * ve0.z + h0.w * ve0.w
                + h1.x * ve1.x + h1.y * ve1.y + h1.z * ve1.z + h1.w * ve1.w
                + h2.x * ve2.x + h2.y * ve2.y + h2.z * ve2.z + h2.w * ve2.w
                + h3.x * ve3.x + h3.y * ve3.y + h3.z * ve3.z + h3.w * ve3.w;

        // 3-step butterfly within the 8-lane group
        p += __shfl_xor_sync(0xFFFFFFFFu, p, 4);
        p += __shfl_xor_sync(0xFFFFFFFFu, p, 2);
        p += __shfl_xor_sync(0xFFFFFFFFu, p, 1);

        // z = sign*dot ; softplus(-z) = max(-z,0) + log1p(exp(-|z|))
        const float z = __int_as_float(__float_as_int(p) ^ flip);
        maxsum += fmaxf(-z, 0.0f);
        const float e = __expf(-fabsf(z));
        prod = __fmaf_rn(prod, e, prod);          // prod *= (1 + e)
    }

    if (sub == 0) out[s] = maxsum + __logf(prod);
}

// Runtime-depth fallback (same structure, dynamic loop)
__global__ __launch_bounds__(256)
void hs_loss_g8_gen(const float* __restrict__ emb,
                    const float* __restrict__ hs,
                    const int*   __restrict__ u,
                    const int*   __restrict__ v,
                    float*       __restrict__ out,
                    int B, int V, int depth)
{
    const int tid    = blockIdx.x * blockDim.x + threadIdx.x;
    const int warpId = tid >> 5;
    const int lane   = tid & 31;
    const int group  = lane >> 3;
    const int sub    = lane & 7;
    const int s      = warpId * 4 + group;
    if (s >= B) return;

    const int vi = v[s];
    const unsigned m = (unsigned)(V + u[s]);
    const float4* vrow = reinterpret_cast<const float4*>(emb + (size_t)vi * 128);
    const float4 ve0 = __ldcs(vrow + sub);
    const float4 ve1 = __ldcs(vrow + 8  + sub);
    const float4 ve2 = __ldcs(vrow + 16 + sub);
    const float4 ve3 = __ldcs(vrow + 24 + sub);

    float maxsum = 0.0f, prod = 1.0f;
    for (int d = 0; d < depth; ++d) {
        const int idx  = (int)(m >> (d + 1)) - 1;
        const int flip = (int)((m >> d) & 1u) << 31;
        const float4* hrow =
            reinterpret_cast<const float4*>(hs + (size_t)idx * 128);
        const float4 h0 = __ldg(hrow + sub);
        const float4 h1 = __ldg(hrow + 8  + sub);
        const float4 h2 = __ldg(hrow + 16 + sub);
        const float4 h3 = __ldg(hrow + 24 + sub);

        float p = h0.x * ve0.x + h0.y * ve0.y + h0.z * ve0.z + h0.w * ve0.w
                + h1.x * ve1.x + h1.y * ve1.y + h1.z * ve1.z + h1.w * ve1.w
                + h2.x * ve2.x + h2.y * ve2.y + h2.z * ve2.z + h2.w * ve2.w
                + h3.x * ve3.x + h3.y * ve3.y + h3.z * ve3.z + h3.w * ve3.w;
        p += __shfl_xor_sync(0xFFFFFFFFu, p, 4);
        p += __shfl_xor_sync(0xFFFFFFFFu, p, 2);
        p += __shfl_xor_sync(0xFFFFFFFFu, p, 1);

        const float z = __int_as_float(__float_as_int(p) ^ flip);
        maxsum += fmaxf(-z, 0.0f);
        const float e = __expf(-fabsf(z));
        prod = __fmaf_rn(prod, e, prod);
    }
    if (sub == 0) out[s] = maxsum + __logf(prod);
}

extern "C" void kernel_launch(void* const* d_in, const int* in_sizes, int n_in,
                              void* d_out, int out_size)
{
    const float* emb = (const float*)d_in[0];   // [V, 128]
    const float* hs  = (const float*)d_in[1];   // [V-1, 128]
    const int*   u   = (const int*)d_in[2];     // [B]
    const int*   v   = (const int*)d_in[3];     // [B]
    float*       out = (float*)d_out;           // [B]

    const int B = in_sizes[2];
    const int V = in_sizes[0] / 128;

    int depth = 0;
    while ((1 << (depth + 1)) <= V) ++depth;

    const int threads = 256;                     // 8 warps = 32 samples/block
    const int warps   = (B + 3) / 4;             // 4 samples per warp
    const int blocks  = (warps * 32 + threads - 1) / threads;

    if (depth == 20) {
        hs_loss_g8<20><<<blocks, threads>>>(emb, hs, u, v, out, B, V);
    } else {
        hs_loss_g8_gen<<<blocks, threads>>>(emb, hs, u, v, out, B, V, depth);
    }
}